// round 2
// baseline (speedup 1.0000x reference)
#include <cuda_runtime.h>

#define NPTS    8192
#define BATCH   8
#define NPOINT  512
#define NSAMPLE 32
#define NT      (BATCH*NPOINT*NSAMPLE)   // 131072 samples

// ---------------- scratch (device globals; no allocation) ----------------
__device__ float g_X0[67u*NT];    // layer0 input features [c][t]
__device__ float g_Y0[64u*NT];    // layer0 raw output (pre-BN)
__device__ float g_Y1[64u*NT];    // layer1 raw output
__device__ float g_Y2[128u*NT];   // layer2 raw output
__device__ float g_newxyz[BATCH*NPOINT*3];   // (b,s,3) centroids
__device__ float g_sum[128];
__device__ float g_sumsq[128];
__device__ float g_scale[128];
__device__ float g_shift[128];

// ---------------- FPS ----------------
// one CTA per batch, 1024 threads, 8 points per thread kept in registers.
// DO NOT change arithmetic here: output 0 verified bit-exact in round 1.
__device__ __forceinline__ void warp_argmax(float& v, int& i) {
    #pragma unroll
    for (int off = 16; off; off >>= 1) {
        float v2 = __shfl_down_sync(0xffffffffu, v, off);
        int   i2 = __shfl_down_sync(0xffffffffu, i, off);
        if (v2 > v || (v2 == v && i2 < i)) { v = v2; i = i2; }
    }
}

__global__ __launch_bounds__(1024) void fps_kernel(const float* __restrict__ xyz,
                                                   float* __restrict__ out_newxyz)
{
    const int b   = blockIdx.x;
    const int tid = threadIdx.x;
    const float* X  = xyz + (size_t)b * 3 * NPTS;
    const float* Yc = X + NPTS;
    const float* Z  = X + 2 * NPTS;

    float px[8], py[8], pz[8], dist[8];
    #pragma unroll
    for (int j = 0; j < 8; j++) {
        int i = tid + j * 1024;
        px[j] = X[i]; py[j] = Yc[i]; pz[j] = Z[i];
        dist[j] = 1e10f;
    }

    __shared__ float s_v[32];
    __shared__ int   s_i[32];
    __shared__ int   s_far;

    // initial far = argmax of x coordinate (first-index ties)
    float bv = -1e30f; int bi = 0;
    #pragma unroll
    for (int j = 0; j < 8; j++) {
        int i = tid + j * 1024;
        if (px[j] > bv) { bv = px[j]; bi = i; }
    }
    {
        warp_argmax(bv, bi);
        int w = tid >> 5;
        if ((tid & 31) == 0) { s_v[w] = bv; s_i[w] = bi; }
        __syncthreads();
        if (w == 0) {
            float v = s_v[tid]; int i = s_i[tid];
            warp_argmax(v, i);
            if (tid == 0) s_far = i;
        }
        __syncthreads();
    }
    int far = s_far;

    for (int s = 0; s < NPOINT; s++) {
        float cx = X[far], cy = Yc[far], cz = Z[far];
        if (tid == 0) {
            out_newxyz[(b * 3 + 0) * NPOINT + s] = cx;
            out_newxyz[(b * 3 + 1) * NPOINT + s] = cy;
            out_newxyz[(b * 3 + 2) * NPOINT + s] = cz;
            g_newxyz[(b * NPOINT + s) * 3 + 0] = cx;
            g_newxyz[(b * NPOINT + s) * 3 + 1] = cy;
            g_newxyz[(b * NPOINT + s) * 3 + 2] = cz;
        }
        float lv = -1e30f; int li = 0;
        #pragma unroll
        for (int j = 0; j < 8; j++) {
            float dx = px[j] - cx, dy = py[j] - cy, dz = pz[j] - cz;
            float d  = fmaf(dz, dz, fmaf(dy, dy, dx * dx));
            float nd = fminf(dist[j], d);
            dist[j] = nd;
            if (nd > lv) { lv = nd; li = tid + j * 1024; }
        }
        warp_argmax(lv, li);
        int w = tid >> 5;
        if ((tid & 31) == 0) { s_v[w] = lv; s_i[w] = li; }
        __syncthreads();
        if (w == 0) {
            float v = s_v[tid]; int i = s_i[tid];
            warp_argmax(v, i);
            if (tid == 0) s_far = i;
        }
        __syncthreads();
        far = s_far;
    }
}

// ---------------- ball query + gather (one warp per (b,s)) ----------------
// Distance must round EXACTLY like the reference:
//   dot  = fma(s2,d2, fma(s1,d1, rn(s0*d0)))          (XLA K=3 fma dot)
//   |v|^2 = rn(rn(rn(x*x) + rn(y*y)) + rn(z*z))       (square then plain adds, NO fma)
//   d    = rn(rn(-2*dot + |src|^2) + |dst|^2)
__global__ __launch_bounds__(256) void ball_gather_kernel(const float* __restrict__ xyz,
                                                          const float* __restrict__ points)
{
    const int w    = blockIdx.x * 8 + (threadIdx.x >> 5);
    const int lane = threadIdx.x & 31;
    const int b = w >> 9;
    const int s = w & 511;

    const float* X  = xyz + (size_t)b * 3 * NPTS;
    const float* Yc = X + NPTS;
    const float* Z  = X + 2 * NPTS;

    const float cx = g_newxyz[(b * NPOINT + s) * 3 + 0];
    const float cy = g_newxyz[(b * NPOINT + s) * 3 + 1];
    const float cz = g_newxyz[(b * NPOINT + s) * 3 + 2];
    // |centroid|^2 : squares then plain adds (no fma), matching jnp.sum(src**2,-1)
    const float cc = __fadd_rn(__fadd_rn(__fmul_rn(cx, cx), __fmul_rn(cy, cy)),
                               __fmul_rn(cz, cz));
    const float r2 = 0.04f;

    __shared__ int nbr_s[8][NSAMPLE];
    int* nbr = nbr_s[threadIdx.x >> 5];

    int found = 0;
    for (int base = 0; base < NPTS; base += 32) {
        int   j  = base + lane;
        float xj = X[j], yj = Yc[j], zj = Z[j];
        // fma-chain dot (XLA dot_general), ascending c
        float dot = fmaf(cz, zj, fmaf(cy, yj, __fmul_rn(cx, xj)));
        // |point|^2 : squares then plain adds (no fma)
        float pp  = __fadd_rn(__fadd_rn(__fmul_rn(xj, xj), __fmul_rn(yj, yj)),
                              __fmul_rn(zj, zj));
        float d   = __fadd_rn(__fadd_rn(__fmul_rn(-2.0f, dot), cc), pp);
        bool in   = !(d > r2);
        unsigned m = __ballot_sync(0xffffffffu, in);
        int pos = found + __popc(m & ((1u << lane) - 1u));
        if (in && pos < NSAMPLE) nbr[pos] = j;
        found += __popc(m);
        if (found >= NSAMPLE) break;
    }
    __syncwarp();
    if (found > NSAMPLE) found = NSAMPLE;
    int j0 = nbr[0];
    int j  = (lane < found) ? nbr[lane] : j0;

    const int t = (b * NPOINT + s) * NSAMPLE + lane;
    g_X0[0u * NT + t] = X[j]  - cx;
    g_X0[1u * NT + t] = Yc[j] - cy;
    g_X0[2u * NT + t] = Z[j]  - cz;
    const float* P = points + (size_t)b * 64 * NPTS;
    #pragma unroll 4
    for (int d = 0; d < 64; d++) {
        g_X0[(size_t)(3 + d) * NT + t] = P[(size_t)d * NPTS + j];
    }
}

// ---------------- fused layer GEMM ----------------
// LAYER selects in/out device buffers. Each thread computes 2 adjacent samples
// (x kept fully in registers), so the W shared-load is amortized over 2 FFMAs.
template<int CIN, int COUT, bool BNIN, int LAYER>
__global__ __launch_bounds__(256) void layer_kernel(const float* __restrict__ W,
                                                    const float* __restrict__ bias)
{
    const float* Xin  = (LAYER == 0) ? g_X0 : (LAYER == 1) ? g_Y0 : g_Y1;
    float*       Yout = (LAYER == 0) ? g_Y0 : (LAYER == 1) ? g_Y1 : g_Y2;

    __shared__ float Ws[COUT * CIN];
    __shared__ float bs[COUT];
    __shared__ float sc[CIN];
    __shared__ float sh[CIN];

    const int tid = threadIdx.x;
    for (int i = tid; i < COUT * CIN; i += 256) Ws[i] = W[i];
    for (int i = tid; i < COUT; i += 256)       bs[i] = bias[i];
    if (BNIN) {
        for (int i = tid; i < CIN; i += 256) { sc[i] = g_scale[i]; sh[i] = g_shift[i]; }
    }
    __syncthreads();

    const int t2 = blockIdx.x * 256 + tid;   // pair index; samples 2*t2, 2*t2+1
    float x0[CIN], x1[CIN];
    #pragma unroll
    for (int c = 0; c < CIN; c++) {
        float2 v = *reinterpret_cast<const float2*>(Xin + (size_t)c * NT + 2 * t2);
        if (BNIN) {
            v.x = fmaxf(0.f, fmaf(v.x, sc[c], sh[c]));
            v.y = fmaxf(0.f, fmaf(v.y, sc[c], sh[c]));
        }
        x0[c] = v.x; x1[c] = v.y;
    }

    float* yp = Yout + 2 * t2;
    for (int o = 0; o < COUT; o++) {
        float a0 = bs[o], a1 = bs[o];
        const float* wr = Ws + o * CIN;
        #pragma unroll
        for (int c = 0; c < CIN; c++) {
            float wv = wr[c];
            a0 = fmaf(wv, x0[c], a0);
            a1 = fmaf(wv, x1[c], a1);
        }
        *reinterpret_cast<float2*>(yp + (size_t)o * NT) = make_float2(a0, a1);
    }
}

// ---------------- per-channel batch statistics ----------------
template<int LAYER>
__global__ __launch_bounds__(256) void stats_kernel()
{
    const float* Y = (LAYER == 0) ? g_Y0 : (LAYER == 1) ? g_Y1 : g_Y2;
    const int c = blockIdx.x;
    const float* p = Y + (size_t)c * NT;
    float s = 0.f, sq = 0.f;
    for (int i = threadIdx.x; i < NT; i += 256) {
        float v = p[i];
        s += v;
        sq = fmaf(v, v, sq);
    }
    __shared__ float rs[8], rq[8];
    #pragma unroll
    for (int off = 16; off; off >>= 1) {
        s  += __shfl_down_sync(0xffffffffu, s,  off);
        sq += __shfl_down_sync(0xffffffffu, sq, off);
    }
    int w = threadIdx.x >> 5;
    if ((threadIdx.x & 31) == 0) { rs[w] = s; rq[w] = sq; }
    __syncthreads();
    if (threadIdx.x == 0) {
        float ts = 0.f, tq = 0.f;
        #pragma unroll
        for (int i = 0; i < 8; i++) { ts += rs[i]; tq += rq[i]; }
        g_sum[c] = ts; g_sumsq[c] = tq;
    }
}

__global__ void finalize_kernel(const float* __restrict__ g, const float* __restrict__ beta, int C)
{
    int c = threadIdx.x;
    if (c < C) {
        float mu  = g_sum[c]   * (1.0f / NT);
        float var = g_sumsq[c] * (1.0f / NT) - mu * mu;
        float rsq = rsqrtf(var + 1e-5f);
        float scv = g[c] * rsq;
        g_scale[c] = scv;
        g_shift[c] = fmaf(-mu, scv, beta[c]);
    }
}

// ---------------- BN + ReLU + max over k ----------------
// one block per (b, o); e = s*32+k is contiguous; each warp round covers one s.
__global__ __launch_bounds__(256) void final_kernel(float* __restrict__ out2)
{
    const int bo = blockIdx.x;
    const int b = bo >> 7;
    const int o = bo & 127;
    const float scv = g_scale[o];
    const float shv = g_shift[o];
    const float* p = g_Y2 + (size_t)o * NT + (size_t)b * (NPOINT * NSAMPLE);
    const int tid  = threadIdx.x;
    const int w    = tid >> 5;
    const int lane = tid & 31;
    for (int r = 0; r < 64; r++) {
        float v = p[tid + r * 256];
        v = fmaxf(0.f, fmaf(v, scv, shv));
        #pragma unroll
        for (int off = 16; off; off >>= 1)
            v = fmaxf(v, __shfl_down_sync(0xffffffffu, v, off));
        if (lane == 0)
            out2[(b * 128 + o) * NPOINT + (w + 8 * r)] = v;
    }
}

// ---------------- launch ----------------
extern "C" void kernel_launch(void* const* d_in, const int* in_sizes, int n_in,
                              void* d_out, int out_size)
{
    (void)in_sizes; (void)n_in; (void)out_size;
    const float* xyz    = (const float*)d_in[0];
    const float* points = (const float*)d_in[1];
    const float* W0 = (const float*)d_in[2];
    const float* b0 = (const float*)d_in[3];
    const float* g0 = (const float*)d_in[4];
    const float* be0= (const float*)d_in[5];
    const float* W1 = (const float*)d_in[6];
    const float* b1 = (const float*)d_in[7];
    const float* g1 = (const float*)d_in[8];
    const float* be1= (const float*)d_in[9];
    const float* W2 = (const float*)d_in[10];
    const float* b2 = (const float*)d_in[11];
    const float* g2 = (const float*)d_in[12];
    const float* be2= (const float*)d_in[13];

    float* out = (float*)d_out;

    fps_kernel<<<BATCH, 1024>>>(xyz, out);
    ball_gather_kernel<<<(BATCH * NPOINT) / 8, 256>>>(xyz, points);

    layer_kernel<67, 64, false, 0><<<NT / 512, 256>>>(W0, b0);
    stats_kernel<0><<<64, 256>>>();
    finalize_kernel<<<1, 64>>>(g0, be0, 64);

    layer_kernel<64, 64, true, 1><<<NT / 512, 256>>>(W1, b1);
    stats_kernel<1><<<64, 256>>>();
    finalize_kernel<<<1, 64>>>(g1, be1, 64);

    layer_kernel<64, 128, true, 2><<<NT / 512, 256>>>(W2, b2);
    stats_kernel<2><<<128, 256>>>();
    finalize_kernel<<<1, 128>>>(g2, be2, 128);

    final_kernel<<<BATCH * 128, 256>>>(out + BATCH * 3 * NPOINT);
}

// round 3
// speedup vs baseline: 1.0042x; 1.0042x over previous
#include <cuda_runtime.h>

#define NPTS    8192
#define BATCH   8
#define NPOINT  512
#define NSAMPLE 32
#define NT      (BATCH*NPOINT*NSAMPLE)   // 131072 samples
#define NSTILE  512                      // sample tiles of 256 in layer kernels

// ---------------- scratch (device globals; no allocation) ----------------
__device__ float g_X0[67u*NT];    // layer0 input features [c][t]
__device__ float g_Y0[64u*NT];    // layer0 raw output (pre-BN)
__device__ float g_Y1[64u*NT];    // layer1 raw output
__device__ float g_Y2[128u*NT];   // layer2 raw output
__device__ float g_newxyz[BATCH*NPOINT*3];   // (b,s,3) centroids
__device__ float g_psum[128*NSTILE];
__device__ float g_psq [128*NSTILE];
__device__ float g_scale[128];
__device__ float g_shift[128];

// ---------------- packed f32x2 helpers (per-half rounding == scalar ops) ---
typedef unsigned long long u64;
__device__ __forceinline__ u64 pk2(float lo, float hi) {
    u64 r; asm("mov.b64 %0,{%1,%2};" : "=l"(r) : "f"(lo), "f"(hi)); return r;
}
__device__ __forceinline__ void upk2(u64 v, float& lo, float& hi) {
    asm("mov.b64 {%0,%1},%2;" : "=f"(lo), "=f"(hi) : "l"(v));
}
__device__ __forceinline__ u64 add2(u64 a, u64 b) {
    u64 r; asm("add.rn.f32x2 %0,%1,%2;" : "=l"(r) : "l"(a), "l"(b)); return r;
}
__device__ __forceinline__ u64 mul2(u64 a, u64 b) {
    u64 r; asm("mul.rn.f32x2 %0,%1,%2;" : "=l"(r) : "l"(a), "l"(b)); return r;
}
__device__ __forceinline__ u64 fma2(u64 a, u64 b, u64 c) {
    u64 r; asm("fma.rn.f32x2 %0,%1,%2,%3;" : "=l"(r) : "l"(a), "l"(b), "l"(c)); return r;
}

// ---------------- FPS ----------------
// one CTA per batch, 1024 threads, 8 points per thread kept in registers.
// Arithmetic verified BIT-EXACT vs reference in round 1; the f32x2 packing
// below computes the identical per-lane roundings (add/mul/fma per half).
__device__ __forceinline__ void warp_argmax(float& v, int& i) {
    #pragma unroll
    for (int off = 16; off; off >>= 1) {
        float v2 = __shfl_down_sync(0xffffffffu, v, off);
        int   i2 = __shfl_down_sync(0xffffffffu, i, off);
        if (v2 > v || (v2 == v && i2 < i)) { v = v2; i = i2; }
    }
}

__global__ __launch_bounds__(1024) void fps_kernel(const float* __restrict__ xyz,
                                                   float* __restrict__ out_newxyz)
{
    const int b   = blockIdx.x;
    const int tid = threadIdx.x;
    const float* X  = xyz + (size_t)b * 3 * NPTS;
    const float* Yc = X + NPTS;
    const float* Z  = X + 2 * NPTS;

    // pack pairs (j=2m, j=2m+1): lo index tid+2m*1024, hi index tid+(2m+1)*1024
    u64 px2[4], py2[4], pz2[4];
    float dist[8];
    float pxs[8];
    #pragma unroll
    for (int j = 0; j < 8; j++) {
        int i = tid + j * 1024;
        pxs[j] = X[i];
        dist[j] = 1e10f;
    }
    #pragma unroll
    for (int m = 0; m < 4; m++) {
        int i0 = tid + (2 * m) * 1024, i1 = i0 + 1024;
        px2[m] = pk2(pxs[2 * m], pxs[2 * m + 1]);
        py2[m] = pk2(Yc[i0], Yc[i1]);
        pz2[m] = pk2(Z[i0],  Z[i1]);
    }

    __shared__ float s_v[32];
    __shared__ int   s_i[32];
    __shared__ int   s_far;

    // initial far = argmax of x coordinate (first-index ties)
    float bv = -1e30f; int bi = 0;
    #pragma unroll
    for (int j = 0; j < 8; j++) {
        int i = tid + j * 1024;
        if (pxs[j] > bv) { bv = pxs[j]; bi = i; }
    }
    {
        warp_argmax(bv, bi);
        int w = tid >> 5;
        if ((tid & 31) == 0) { s_v[w] = bv; s_i[w] = bi; }
        __syncthreads();
        if (w == 0) {
            float v = s_v[tid]; int i = s_i[tid];
            warp_argmax(v, i);
            if (tid == 0) s_far = i;
        }
        __syncthreads();
    }
    int far = s_far;

    // zero not needed anymore (no atomics) — nothing here.

    for (int s = 0; s < NPOINT; s++) {
        float cx = X[far], cy = Yc[far], cz = Z[far];
        if (tid == 0) {
            out_newxyz[(b * 3 + 0) * NPOINT + s] = cx;
            out_newxyz[(b * 3 + 1) * NPOINT + s] = cy;
            out_newxyz[(b * 3 + 2) * NPOINT + s] = cz;
            g_newxyz[(b * NPOINT + s) * 3 + 0] = cx;
            g_newxyz[(b * NPOINT + s) * 3 + 1] = cy;
            g_newxyz[(b * NPOINT + s) * 3 + 2] = cz;
        }
        const u64 ncx2 = pk2(-cx, -cx);
        const u64 ncy2 = pk2(-cy, -cy);
        const u64 ncz2 = pk2(-cz, -cz);
        float lv = -1e30f; int li = 0;
        #pragma unroll
        for (int m = 0; m < 4; m++) {
            u64 dx2 = add2(px2[m], ncx2);          // rn(px - cx) per half
            u64 dy2 = add2(py2[m], ncy2);
            u64 dz2 = add2(pz2[m], ncz2);
            u64 d2  = fma2(dz2, dz2, fma2(dy2, dy2, mul2(dx2, dx2)));
            float d0, d1; upk2(d2, d0, d1);
            float nd0 = fminf(dist[2 * m], d0);     dist[2 * m]     = nd0;
            if (nd0 > lv) { lv = nd0; li = tid + (2 * m) * 1024; }
            float nd1 = fminf(dist[2 * m + 1], d1); dist[2 * m + 1] = nd1;
            if (nd1 > lv) { lv = nd1; li = tid + (2 * m + 1) * 1024; }
        }
        warp_argmax(lv, li);
        int w = tid >> 5;
        if ((tid & 31) == 0) { s_v[w] = lv; s_i[w] = li; }
        __syncthreads();
        if (w == 0) {
            float v = s_v[tid]; int i = s_i[tid];
            warp_argmax(v, i);
            if (tid == 0) s_far = i;
        }
        __syncthreads();
        far = s_far;
    }
}

// ---------------- ball query + gather (one warp per (b,s)) ----------------
// Distance rounds EXACTLY like the reference (verified round 2):
//   dot  = fma(c2,p2, fma(c1,p1, rn(c0*p0)))
//   |v|^2 = rn(rn(x*x + y*y) + z*z)  built from plain mul/add (NO fma)
//   d    = rn(rn(-2*dot + |src|^2) + |dst|^2)
__global__ __launch_bounds__(256) void ball_gather_kernel(const float* __restrict__ xyz,
                                                          const float* __restrict__ points)
{
    const int w    = blockIdx.x * 8 + (threadIdx.x >> 5);
    const int lane = threadIdx.x & 31;
    const int b = w >> 9;
    const int s = w & 511;

    const float* X  = xyz + (size_t)b * 3 * NPTS;
    const float* Yc = X + NPTS;
    const float* Z  = X + 2 * NPTS;

    const float cx = g_newxyz[(b * NPOINT + s) * 3 + 0];
    const float cy = g_newxyz[(b * NPOINT + s) * 3 + 1];
    const float cz = g_newxyz[(b * NPOINT + s) * 3 + 2];
    const float cc = __fadd_rn(__fadd_rn(__fmul_rn(cx, cx), __fmul_rn(cy, cy)),
                               __fmul_rn(cz, cz));
    const float r2 = 0.04f;

    __shared__ int nbr_s[8][NSAMPLE];
    int* nbr = nbr_s[threadIdx.x >> 5];

    int found = 0;
    for (int base = 0; base < NPTS; base += 32) {
        int   j  = base + lane;
        float xj = X[j], yj = Yc[j], zj = Z[j];
        float dot = fmaf(cz, zj, fmaf(cy, yj, __fmul_rn(cx, xj)));
        float pp  = __fadd_rn(__fadd_rn(__fmul_rn(xj, xj), __fmul_rn(yj, yj)),
                              __fmul_rn(zj, zj));
        float d   = __fadd_rn(__fadd_rn(__fmul_rn(-2.0f, dot), cc), pp);
        bool in   = !(d > r2);
        unsigned m = __ballot_sync(0xffffffffu, in);
        int pos = found + __popc(m & ((1u << lane) - 1u));
        if (in && pos < NSAMPLE) nbr[pos] = j;
        found += __popc(m);
        if (found >= NSAMPLE) break;
    }
    __syncwarp();
    if (found > NSAMPLE) found = NSAMPLE;
    int j0 = nbr[0];
    int j  = (lane < found) ? nbr[lane] : j0;

    const int t = (b * NPOINT + s) * NSAMPLE + lane;
    g_X0[0u * NT + t] = X[j]  - cx;
    g_X0[1u * NT + t] = Yc[j] - cy;
    g_X0[2u * NT + t] = Z[j]  - cz;
    const float* P = points + (size_t)b * 64 * NPTS;
    #pragma unroll 4
    for (int d = 0; d < 64; d++) {
        g_X0[(size_t)(3 + d) * NT + t] = P[(size_t)d * NPTS + j];
    }
}

// ---------------- fused layer GEMM, 8x8 register blocked, fused BN stats ---
// Block = 256 threads (tx=lane 0..31, warp wp=0..7). Tile = 256 samples x 64
// outputs. Thread computes 8 samples (tx + 32k) x 8 outputs (wp*8+j).
// X staged through shared in 16-channel chunks; input BN+ReLU applied once at
// staging. Epilogue reduces per-channel sum/sumsq per block into g_psum/g_psq
// (deterministic; no atomics).
#define CCH 16
template<int CIN, bool BNIN, int LAYER>
__global__ __launch_bounds__(256, 2) void layer_kernel(const float* __restrict__ W,
                                                       const float* __restrict__ bias)
{
    const float* Xin  = (LAYER == 0) ? g_X0 : (LAYER == 1) ? g_Y0 : g_Y1;
    float*       Yout = (LAYER == 0) ? g_Y0 : (LAYER == 1) ? g_Y1 : g_Y2;

    __shared__ float Ws[64 * CIN];
    __shared__ float bs2[64];
    __shared__ float Xs[CCH * 256];
    __shared__ float sc[CIN];
    __shared__ float sh[CIN];

    const int tid   = threadIdx.x;
    const int tx    = tid & 31;
    const int wp    = tid >> 5;
    const int obase = blockIdx.y * 64;
    const int tbase = blockIdx.x * 256;

    const float* Wg = W + (size_t)obase * CIN;
    for (int i = tid; i < 64 * CIN; i += 256) Ws[i] = Wg[i];
    for (int i = tid; i < 64; i += 256)       bs2[i] = bias[obase + i];
    if (BNIN) {
        for (int i = tid; i < CIN; i += 256) { sc[i] = g_scale[i]; sh[i] = g_shift[i]; }
    }
    __syncthreads();

    float acc[8][8];
    {
        float b0[8];
        #pragma unroll
        for (int j = 0; j < 8; j++) b0[j] = bs2[wp * 8 + j];
        #pragma unroll
        for (int k = 0; k < 8; k++)
            #pragma unroll
            for (int j = 0; j < 8; j++) acc[k][j] = b0[j];
    }

    for (int c0 = 0; c0 < CIN; c0 += CCH) {
        const int cn = (CIN - c0 < CCH) ? (CIN - c0) : CCH;
        __syncthreads();
        // stage cn rows of 256 samples (float4 coalesced)
        for (int e = tid; e < cn * 64; e += 256) {
            int cc   = e >> 6;
            int col4 = (e & 63) << 2;
            float4 v = *reinterpret_cast<const float4*>(
                Xin + (size_t)(c0 + cc) * NT + tbase + col4);
            if (BNIN) {
                float s = sc[c0 + cc], h = sh[c0 + cc];
                v.x = fmaxf(0.f, fmaf(v.x, s, h));
                v.y = fmaxf(0.f, fmaf(v.y, s, h));
                v.z = fmaxf(0.f, fmaf(v.z, s, h));
                v.w = fmaxf(0.f, fmaf(v.w, s, h));
            }
            *reinterpret_cast<float4*>(Xs + cc * 256 + col4) = v;
        }
        __syncthreads();
        for (int cc = 0; cc < cn; cc++) {
            float xv[8];
            #pragma unroll
            for (int k = 0; k < 8; k++) xv[k] = Xs[cc * 256 + tx + 32 * k];
            #pragma unroll
            for (int j = 0; j < 8; j++) {
                float wv = Ws[(wp * 8 + j) * CIN + c0 + cc];
                #pragma unroll
                for (int k = 0; k < 8; k++)
                    acc[k][j] = fmaf(wv, xv[k], acc[k][j]);
            }
        }
    }

    // write Y (coalesced per (j,k): lanes consecutive over tx)
    #pragma unroll
    for (int j = 0; j < 8; j++) {
        const int o = obase + wp * 8 + j;
        float* yp = Yout + (size_t)o * NT + tbase + tx;
        #pragma unroll
        for (int k = 0; k < 8; k++) yp[32 * k] = acc[k][j];
    }

    // fused per-channel partial stats for this block's 256 samples
    #pragma unroll
    for (int j = 0; j < 8; j++) {
        float s = 0.f, q = 0.f;
        #pragma unroll
        for (int k = 0; k < 8; k++) {
            float v = acc[k][j];
            s += v;
            q = fmaf(v, v, q);
        }
        #pragma unroll
        for (int off = 16; off; off >>= 1) {
            s += __shfl_down_sync(0xffffffffu, s, off);
            q += __shfl_down_sync(0xffffffffu, q, off);
        }
        if (tx == 0) {
            const int o = obase + wp * 8 + j;
            g_psum[o * NSTILE + blockIdx.x] = s;
            g_psq [o * NSTILE + blockIdx.x] = q;
        }
    }
}

// ---------------- reduce partials -> BN scale/shift ----------------
__global__ __launch_bounds__(256) void finalize_kernel(const float* __restrict__ g,
                                                       const float* __restrict__ beta)
{
    const int c = blockIdx.x;
    float s = 0.f, q = 0.f;
    for (int i = threadIdx.x; i < NSTILE; i += 256) {
        s += g_psum[c * NSTILE + i];
        q += g_psq [c * NSTILE + i];
    }
    __shared__ float rs[8], rq[8];
    #pragma unroll
    for (int off = 16; off; off >>= 1) {
        s += __shfl_down_sync(0xffffffffu, s, off);
        q += __shfl_down_sync(0xffffffffu, q, off);
    }
    int w = threadIdx.x >> 5;
    if ((threadIdx.x & 31) == 0) { rs[w] = s; rq[w] = q; }
    __syncthreads();
    if (threadIdx.x == 0) {
        float ts = 0.f, tq = 0.f;
        #pragma unroll
        for (int i = 0; i < 8; i++) { ts += rs[i]; tq += rq[i]; }
        float mu  = ts * (1.0f / NT);
        float var = tq * (1.0f / NT) - mu * mu;
        float rsq = rsqrtf(var + 1e-5f);
        float scv = g[c] * rsq;
        g_scale[c] = scv;
        g_shift[c] = fmaf(-mu, scv, beta[c]);
    }
}

// ---------------- BN + ReLU + max over k ----------------
__global__ __launch_bounds__(256) void final_kernel(float* __restrict__ out2)
{
    const int bo = blockIdx.x;
    const int b = bo >> 7;
    const int o = bo & 127;
    const float scv = g_scale[o];
    const float shv = g_shift[o];
    const float* p = g_Y2 + (size_t)o * NT + (size_t)b * (NPOINT * NSAMPLE);
    const int tid  = threadIdx.x;
    const int w    = tid >> 5;
    const int lane = tid & 31;
    for (int r = 0; r < 64; r++) {
        float v = p[tid + r * 256];
        v = fmaxf(0.f, fmaf(v, scv, shv));
        #pragma unroll
        for (int off = 16; off; off >>= 1)
            v = fmaxf(v, __shfl_down_sync(0xffffffffu, v, off));
        if (lane == 0)
            out2[(b * 128 + o) * NPOINT + (w + 8 * r)] = v;
    }
}

// ---------------- launch ----------------
extern "C" void kernel_launch(void* const* d_in, const int* in_sizes, int n_in,
                              void* d_out, int out_size)
{
    (void)in_sizes; (void)n_in; (void)out_size;
    const float* xyz    = (const float*)d_in[0];
    const float* points = (const float*)d_in[1];
    const float* W0 = (const float*)d_in[2];
    const float* b0 = (const float*)d_in[3];
    const float* g0 = (const float*)d_in[4];
    const float* be0= (const float*)d_in[5];
    const float* W1 = (const float*)d_in[6];
    const float* b1 = (const float*)d_in[7];
    const float* g1 = (const float*)d_in[8];
    const float* be1= (const float*)d_in[9];
    const float* W2 = (const float*)d_in[10];
    const float* b2 = (const float*)d_in[11];
    const float* g2 = (const float*)d_in[12];
    const float* be2= (const float*)d_in[13];

    float* out = (float*)d_out;

    fps_kernel<<<BATCH, 1024>>>(xyz, out);
    ball_gather_kernel<<<(BATCH * NPOINT) / 8, 256>>>(xyz, points);

    layer_kernel<67, false, 0><<<dim3(NSTILE, 1), 256>>>(W0, b0);
    finalize_kernel<<<64, 256>>>(g0, be0);

    layer_kernel<64, true, 1><<<dim3(NSTILE, 1), 256>>>(W1, b1);
    finalize_kernel<<<64, 256>>>(g1, be1);

    layer_kernel<64, true, 2><<<dim3(NSTILE, 2), 256>>>(W2, b2);
    finalize_kernel<<<128, 256>>>(g2, be2);

    final_kernel<<<BATCH * 128, 256>>>(out + BATCH * 3 * NPOINT);
}